// round 7
// baseline (speedup 1.0000x reference)
#include <cuda_runtime.h>
#include <cuda_fp16.h>
#include <cstdint>

#define DEV_INLINE __device__ __forceinline__

// ---------------- problem sizes ----------------
#define BSZ   65536
#define Hd    1024
#define NEXP  10
#define NT2   8        // 1024 / 128 N-tiles
#define TKH   64       // halves of K per pipeline chunk (128 bytes/row)
#define NCHUNK (Hd / TKH)   // 16

// ---------------- scratch (static __device__ arrays; no allocs) ------------
__device__ __align__(256) __half  g_h1[(size_t)BSZ * Hd];     // 128 MB
__device__ __align__(256) __half  g_W2h[Hd * Hd];             // 2 MB
__device__ __align__(256) float2  g_partial[(size_t)NT2 * BSZ]; // 4 MB

// ---------------- PTX helpers (base sm_103 target only!) ----------------
DEV_INLINE uint32_t smem_u32(const void* p) {
    uint32_t a;
    asm("{ .reg .u64 t; cvta.to.shared.u64 t, %1; cvt.u32.u64 %0, t; }"
        : "=r"(a) : "l"(p));
    return a;
}

#define CP_ASYNC16(saddr, gptr) \
    asm volatile("cp.async.cg.shared.global [%0], [%1], 16;" \
                 :: "r"(saddr), "l"(gptr) : "memory")
#define CP_COMMIT() asm volatile("cp.async.commit_group;" ::: "memory")
#define CP_WAIT(N)  asm volatile("cp.async.wait_group %0;" :: "n"(N) : "memory")

#define LDMATRIX_X4(r0, r1, r2, r3, addr) \
    asm volatile("ldmatrix.sync.aligned.m8n8.x4.shared.b16 {%0,%1,%2,%3}, [%4];" \
                 : "=r"(r0), "=r"(r1), "=r"(r2), "=r"(r3) : "r"(addr))

#define MMA16816(c0, c1, c2, c3, a0, a1, a2, a3, b0, b1) \
    asm volatile("mma.sync.aligned.m16n8k16.row.col.f32.f16.f16.f32 " \
                 "{%0,%1,%2,%3}, {%4,%5,%6,%7}, {%8,%9}, {%0,%1,%2,%3};" \
                 : "+f"(c0), "+f"(c1), "+f"(c2), "+f"(c3) \
                 : "r"(a0), "r"(a1), "r"(a2), "r"(a3), "r"(b0), "r"(b1))

DEV_INLINE uint32_t sw128(uint32_t byo) { return byo ^ ((byo >> 3) & 0x70); }

// ---------------- f32x2 packed math (sm_103a die, base-target encodable) ---
DEV_INLINE unsigned long long pk2(float a, float b) {
    unsigned long long r;
    asm("mov.b64 %0, {%1, %2};" : "=l"(r) : "f"(a), "f"(b));
    return r;
}
DEV_INLINE void upk2(float& a, float& b, unsigned long long v) {
    asm("mov.b64 {%0, %1}, %2;" : "=f"(a), "=f"(b) : "l"(v));
}
#define FMA2(d, a, b, c) \
    asm("fma.rn.f32x2 %0, %1, %2, %3;" : "=l"(d) : "l"(a), "l"(b), "l"(c))

// ============================================================================
// Kernel 1: W2 (fp32, [N,K] row-major, K contiguous) -> fp16
// ============================================================================
__global__ void __launch_bounds__(256) convert_w2_kernel(const float* __restrict__ W2) {
    int i = (blockIdx.x * 256 + threadIdx.x) * 4;
    float4 v = *reinterpret_cast<const float4*>(W2 + i);
    __half2 h0 = __floats2half2_rn(v.x, v.y);
    __half2 h1 = __floats2half2_rn(v.z, v.w);
    uint2 o;
    o.x = *reinterpret_cast<uint32_t*>(&h0);
    o.y = *reinterpret_cast<uint32_t*>(&h1);
    *reinterpret_cast<uint2*>(g_W2h + i) = o;
}

// ============================================================================
// Kernel 2: h1 = relu(delta*W1 + b1 + sum_j oh_j*(phi*Wmeta[j] + bmeta[j]))
// ============================================================================
__global__ void __launch_bounds__(256) h1_kernel(
    const float* __restrict__ x, const float* __restrict__ W1,
    const float* __restrict__ b1, const float* __restrict__ Wm,
    const float* __restrict__ bm)
{
    __shared__ float xs[128 * 12];
    const int tid = threadIdx.x;
    const int b0 = blockIdx.x * 128;

    for (int i = tid; i < 128 * 12; i += 256) xs[i] = x[(size_t)b0 * 12 + i];

    const int k0 = tid * 4;
    float4 w1v = *reinterpret_cast<const float4*>(W1 + k0);
    float4 b1v = *reinterpret_cast<const float4*>(b1 + k0);
    unsigned long long w1A = pk2(w1v.x, w1v.y), w1B = pk2(w1v.z, w1v.w);
    unsigned long long b1A = pk2(b1v.x, b1v.y), b1B = pk2(b1v.z, b1v.w);

    unsigned long long wmA[NEXP], wmB[NEXP], bmA[NEXP], bmB[NEXP];
#pragma unroll
    for (int j = 0; j < NEXP; j++) {
        float4 w = *reinterpret_cast<const float4*>(Wm + j * Hd + k0);
        float4 b = *reinterpret_cast<const float4*>(bm + j * Hd + k0);
        wmA[j] = pk2(w.x, w.y); wmB[j] = pk2(w.z, w.w);
        bmA[j] = pk2(b.x, b.y); bmB[j] = pk2(b.z, b.w);
    }
    __syncthreads();

    for (int r = 0; r < 128; r++) {
        const float* xr = xs + r * 12;
        float delta = xr[10], phi = xr[11];
        unsigned long long d2 = pk2(delta, delta), p2 = pk2(phi, phi);
        unsigned long long aA, aB, t;
        FMA2(aA, d2, w1A, b1A);
        FMA2(aB, d2, w1B, b1B);
#pragma unroll
        for (int j = 0; j < NEXP; j++) {
            unsigned long long o2 = pk2(xr[j], xr[j]);
            FMA2(t, p2, wmA[j], bmA[j]);
            FMA2(aA, o2, t, aA);
            FMA2(t, p2, wmB[j], bmB[j]);
            FMA2(aB, o2, t, aB);
        }
        float a0, a1, a2, a3;
        upk2(a0, a1, aA); upk2(a2, a3, aB);
        __half2 h01 = __floats2half2_rn(fmaxf(a0, 0.f), fmaxf(a1, 0.f));
        __half2 h23 = __floats2half2_rn(fmaxf(a2, 0.f), fmaxf(a3, 0.f));
        uint2 o;
        o.x = *reinterpret_cast<uint32_t*>(&h01);
        o.y = *reinterpret_cast<uint32_t*>(&h23);
        *reinterpret_cast<uint2*>(g_h1 + (size_t)(b0 + r) * Hd + k0) = o;
    }
}

// ============================================================================
// Kernel 3: GEMM2 (mma.sync fp16) + bias + relu + fused W3 dot -> partials
// grid = (8 ntiles, 512 mblocks); CTA 128M x 128N, 8 warps (warp tile 32x64).
// ============================================================================
#define OFF_B2S 0
#define OFF_W30 512
#define OFF_W31 1024
#define OFF_RED 1536
#define OFF_STG 4096
#define STG_BYTES 32768          // A 16K | B 16K per stage
#define GEMM_SMEM (OFF_STG + 2 * STG_BYTES)   // 69632

__global__ void __launch_bounds__(256, 1) gemm_kernel(
    const float* __restrict__ b2, const float* __restrict__ W3)
{
    extern __shared__ char smem[];
    const uint32_t sb = smem_u32(smem);
    const int tid = threadIdx.x, wid = tid >> 5, lane = tid & 31;
    const int ntile = blockIdx.x, mblock = blockIdx.y;
    const int m0 = mblock * 128, n0 = ntile * 128;
    const int warp_m = (wid & 3) * 32;       // 32 rows / warp
    const int warp_n = (wid >> 2) * 64;      // 64 cols / warp

    float* b2s = reinterpret_cast<float*>(smem + OFF_B2S);
    float* w30 = reinterpret_cast<float*>(smem + OFF_W30);
    float* w31 = reinterpret_cast<float*>(smem + OFF_W31);
    float2* red = reinterpret_cast<float2*>(smem + OFF_RED);

    if (tid < 128) {
        b2s[tid] = b2[n0 + tid];
        w30[tid] = W3[n0 + tid];
        w31[tid] = W3[Hd + n0 + tid];
    }

    const __half* Ag = g_h1 + (size_t)m0 * Hd;
    const __half* Bg = g_W2h + (size_t)n0 * Hd;

    // per-thread gmem/smem segment: r = idx>>3 (row 0..127), c = idx&7 (16B seg)
    auto issue_chunk = [&](int kc, int s) {
        const int koff = kc * TKH;
        const uint32_t stgA = sb + OFF_STG + s * STG_BYTES;
        const uint32_t stgB = stgA + 16384;
#pragma unroll
        for (int i = 0; i < 4; i++) {
            int idx = tid + 256 * i;
            int r = idx >> 3, c = idx & 7;
            uint32_t so = sw128(r * 128 + c * 16);
            CP_ASYNC16(stgA + so, Ag + (size_t)r * Hd + koff + c * 8);
        }
#pragma unroll
        for (int i = 0; i < 4; i++) {
            int idx = tid + 256 * i;
            int r = idx >> 3, c = idx & 7;
            uint32_t so = sw128(r * 128 + c * 16);
            CP_ASYNC16(stgB + so, Bg + (size_t)r * Hd + koff + c * 8);
        }
        CP_COMMIT();
    };

    float c[2][8][4];
#pragma unroll
    for (int i = 0; i < 2; i++)
#pragma unroll
        for (int j = 0; j < 8; j++)
#pragma unroll
            for (int q = 0; q < 4; q++) c[i][j][q] = 0.f;

    // lane-constant ldmatrix address components
    const int a_row = lane & 15;             // A: rows base+0..15
    const int a_seg = (lane >> 4) * 16;      // k-halfstep byte offset (0/16)
    const int b_row = (lane & 7) + ((lane & 16) >> 1);   // B: n-rows base+{0..7,8..15}
    const int b_seg = ((lane >> 3) & 1) * 16;

    issue_chunk(0, 0);

    for (int k = 0; k < NCHUNK; k++) {
        const int s = k & 1;
        if (k + 1 < NCHUNK) { issue_chunk(k + 1, s ^ 1); CP_WAIT(1); }
        else                { CP_WAIT(0); }
        __syncthreads();

        const uint32_t stgA = sb + OFF_STG + s * STG_BYTES;
        const uint32_t stgB = stgA + 16384;

#pragma unroll
        for (int kk = 0; kk < 4; kk++) {               // 4 x k16 steps
            uint32_t a[2][4];
#pragma unroll
            for (int i = 0; i < 2; i++) {
                uint32_t byo = (warp_m + i * 16 + a_row) * 128 + kk * 32 + a_seg;
                LDMATRIX_X4(a[i][0], a[i][1], a[i][2], a[i][3], stgA + sw128(byo));
            }
            uint32_t bfr[8][2];
#pragma unroll
            for (int jj = 0; jj < 4; jj++) {           // 2 n-frags per x4
                uint32_t byo = (warp_n + jj * 16 + b_row) * 128 + kk * 32 + b_seg;
                uint32_t r0, r1, r2, r3;
                LDMATRIX_X4(r0, r1, r2, r3, stgB + sw128(byo));
                bfr[jj * 2][0] = r0;     bfr[jj * 2][1] = r1;
                bfr[jj * 2 + 1][0] = r2; bfr[jj * 2 + 1][1] = r3;
            }
#pragma unroll
            for (int i = 0; i < 2; i++)
#pragma unroll
                for (int j = 0; j < 8; j++)
                    MMA16816(c[i][j][0], c[i][j][1], c[i][j][2], c[i][j][3],
                             a[i][0], a[i][1], a[i][2], a[i][3],
                             bfr[j][0], bfr[j][1]);
        }
        __syncthreads();
    }

    // ---- epilogue: relu(c + b2) dot W3 cols, fused in registers ----
    float o0[4] = {0.f, 0.f, 0.f, 0.f}, o1[4] = {0.f, 0.f, 0.f, 0.f};
#pragma unroll
    for (int i = 0; i < 2; i++) {
#pragma unroll
        for (int j = 0; j < 8; j++) {
            int cb = warp_n + j * 8 + (lane & 3) * 2;
            float bb0 = b2s[cb], bb1 = b2s[cb + 1];
            float wa0 = w30[cb], wa1 = w30[cb + 1];
            float wb0 = w31[cb], wb1 = w31[cb + 1];
            float v0 = fmaxf(c[i][j][0] + bb0, 0.f);
            float v1 = fmaxf(c[i][j][1] + bb1, 0.f);
            o0[i * 2]     = fmaf(v0, wa0, fmaf(v1, wa1, o0[i * 2]));
            o1[i * 2]     = fmaf(v0, wb0, fmaf(v1, wb1, o1[i * 2]));
            float v2 = fmaxf(c[i][j][2] + bb0, 0.f);
            float v3 = fmaxf(c[i][j][3] + bb1, 0.f);
            o0[i * 2 + 1] = fmaf(v2, wa0, fmaf(v3, wa1, o0[i * 2 + 1]));
            o1[i * 2 + 1] = fmaf(v2, wb0, fmaf(v3, wb1, o1[i * 2 + 1]));
        }
    }
    // quad reduce (sum over lane&3)
#pragma unroll
    for (int q = 0; q < 4; q++) {
        o0[q] += __shfl_xor_sync(0xffffffffu, o0[q], 1);
        o0[q] += __shfl_xor_sync(0xffffffffu, o0[q], 2);
        o1[q] += __shfl_xor_sync(0xffffffffu, o1[q], 1);
        o1[q] += __shfl_xor_sync(0xffffffffu, o1[q], 2);
    }
    __syncthreads();                 // stages dead; reuse smem ordering
    if ((wid >> 2) == 1 && (lane & 3) == 0) {
#pragma unroll
        for (int q = 0; q < 4; q++) {
            int rl = warp_m + q * 8 + (lane >> 2);
            red[rl] = make_float2(o0[q], o1[q]);
        }
    }
    __syncthreads();
    if ((wid >> 2) == 0 && (lane & 3) == 0) {
#pragma unroll
        for (int q = 0; q < 4; q++) {
            int rl = warp_m + q * 8 + (lane >> 2);
            float2 r = red[rl];
            g_partial[(size_t)ntile * BSZ + m0 + rl] =
                make_float2(o0[q] + r.x, o1[q] + r.y);
        }
    }
}

// ============================================================================
// Kernel 4: reduce partials over 8 ntiles, add b3 -> out (B x 2 fp32)
// ============================================================================
__global__ void __launch_bounds__(256) reduce_kernel(
    const float* __restrict__ b3, float* __restrict__ out)
{
    int i = blockIdx.x * 256 + threadIdx.x;          // 0..65535
    float s0 = b3[0], s1 = b3[1];
#pragma unroll
    for (int t = 0; t < NT2; t++) {
        float2 p = g_partial[(size_t)t * BSZ + i];
        s0 += p.x; s1 += p.y;
    }
    out[2 * i]     = s0;
    out[2 * i + 1] = s1;
}

// ============================================================================
extern "C" void kernel_launch(void* const* d_in, const int* in_sizes, int n_in,
                              void* d_out, int out_size)
{
    const float* x   = (const float*)d_in[0];
    const float* W1  = (const float*)d_in[1];
    const float* b1  = (const float*)d_in[2];
    const float* Wm  = (const float*)d_in[3];
    const float* bm  = (const float*)d_in[4];
    const float* W2  = (const float*)d_in[5];
    const float* b2  = (const float*)d_in[6];
    const float* W3  = (const float*)d_in[7];
    const float* b3  = (const float*)d_in[8];
    float* out = (float*)d_out;

    cudaFuncSetAttribute(gemm_kernel, cudaFuncAttributeMaxDynamicSharedMemorySize, GEMM_SMEM);

    convert_w2_kernel<<<Hd * Hd / (256 * 4), 256>>>(W2);
    h1_kernel<<<BSZ / 128, 256>>>(x, W1, b1, Wm, bm);
    gemm_kernel<<<dim3(NT2, BSZ / 128), 256, GEMM_SMEM>>>(b2, W3);
    reduce_kernel<<<BSZ / 256, 256>>>(b3, out);
}

// round 9
// speedup vs baseline: 1.1741x; 1.1741x over previous
#include <cuda_runtime.h>
#include <cuda_fp16.h>
#include <cstdint>

#define DEV_INLINE __device__ __forceinline__

// ---------------- problem sizes ----------------
#define BSZ   65536
#define Hd    1024
#define NEXP  10
#define NT    4        // 1024 / 256 N-tiles
#define TKH   64       // halves of K per pipeline chunk (128 bytes/row)
#define NCHUNK (Hd / TKH)   // 16
#define NSTG  3

// ---------------- scratch (static __device__ arrays; no allocs) ------------
__device__ __align__(256) __half  g_h1[(size_t)BSZ * Hd];     // 128 MB
__device__ __align__(256) __half  g_W2h[Hd * Hd];             // 2 MB
__device__ __align__(256) float2  g_partial[(size_t)NT * BSZ]; // 2 MB

// ---------------- PTX helpers (base sm_103 target only) ----------------
DEV_INLINE uint32_t smem_u32(const void* p) {
    uint32_t a;
    asm("{ .reg .u64 t; cvta.to.shared.u64 t, %1; cvt.u32.u64 %0, t; }"
        : "=r"(a) : "l"(p));
    return a;
}

#define CP_ASYNC16(saddr, gptr) \
    asm volatile("cp.async.cg.shared.global [%0], [%1], 16;" \
                 :: "r"(saddr), "l"(gptr) : "memory")
#define CP_COMMIT() asm volatile("cp.async.commit_group;" ::: "memory")
#define CP_WAIT(N)  asm volatile("cp.async.wait_group %0;" :: "n"(N) : "memory")

#define LDMATRIX_X4(r0, r1, r2, r3, addr) \
    asm volatile("ldmatrix.sync.aligned.m8n8.x4.shared.b16 {%0,%1,%2,%3}, [%4];" \
                 : "=r"(r0), "=r"(r1), "=r"(r2), "=r"(r3) : "r"(addr))

#define MMA16816(c0, c1, c2, c3, a0, a1, a2, a3, b0, b1) \
    asm volatile("mma.sync.aligned.m16n8k16.row.col.f32.f16.f16.f32 " \
                 "{%0,%1,%2,%3}, {%4,%5,%6,%7}, {%8,%9}, {%0,%1,%2,%3};" \
                 : "+f"(c0), "+f"(c1), "+f"(c2), "+f"(c3) \
                 : "r"(a0), "r"(a1), "r"(a2), "r"(a3), "r"(b0), "r"(b1))

DEV_INLINE uint32_t sw128(uint32_t byo) { return byo ^ ((byo >> 3) & 0x70); }

// ---------------- f32x2 packed math ----------------
DEV_INLINE unsigned long long pk2(float a, float b) {
    unsigned long long r;
    asm("mov.b64 %0, {%1, %2};" : "=l"(r) : "f"(a), "f"(b));
    return r;
}
DEV_INLINE void upk2(float& a, float& b, unsigned long long v) {
    asm("mov.b64 {%0, %1}, %2;" : "=f"(a), "=f"(b) : "l"(v));
}
#define FMA2(d, a, b, c) \
    asm("fma.rn.f32x2 %0, %1, %2, %3;" : "=l"(d) : "l"(a), "l"(b), "l"(c))

// ============================================================================
// Kernel 1: W2 (fp32, [N,K] row-major, K contiguous) -> fp16
// ============================================================================
__global__ void __launch_bounds__(256) convert_w2_kernel(const float* __restrict__ W2) {
    int i = (blockIdx.x * 256 + threadIdx.x) * 4;
    float4 v = *reinterpret_cast<const float4*>(W2 + i);
    __half2 h0 = __floats2half2_rn(v.x, v.y);
    __half2 h1 = __floats2half2_rn(v.z, v.w);
    uint2 o;
    o.x = *reinterpret_cast<uint32_t*>(&h0);
    o.y = *reinterpret_cast<uint32_t*>(&h1);
    *reinterpret_cast<uint2*>(g_W2h + i) = o;
}

// ============================================================================
// Kernel 2: h1 = relu(delta*W1 + b1 + sum_j oh_j*(phi*Wmeta[j] + bmeta[j]))
// ============================================================================
__global__ void __launch_bounds__(256) h1_kernel(
    const float* __restrict__ x, const float* __restrict__ W1,
    const float* __restrict__ b1, const float* __restrict__ Wm,
    const float* __restrict__ bm)
{
    __shared__ float xs[128 * 12];
    const int tid = threadIdx.x;
    const int b0 = blockIdx.x * 128;

    for (int i = tid; i < 128 * 12; i += 256) xs[i] = x[(size_t)b0 * 12 + i];

    const int k0 = tid * 4;
    float4 w1v = *reinterpret_cast<const float4*>(W1 + k0);
    float4 b1v = *reinterpret_cast<const float4*>(b1 + k0);
    unsigned long long w1A = pk2(w1v.x, w1v.y), w1B = pk2(w1v.z, w1v.w);
    unsigned long long b1A = pk2(b1v.x, b1v.y), b1B = pk2(b1v.z, b1v.w);

    unsigned long long wmA[NEXP], wmB[NEXP], bmA[NEXP], bmB[NEXP];
#pragma unroll
    for (int j = 0; j < NEXP; j++) {
        float4 w = *reinterpret_cast<const float4*>(Wm + j * Hd + k0);
        float4 b = *reinterpret_cast<const float4*>(bm + j * Hd + k0);
        wmA[j] = pk2(w.x, w.y); wmB[j] = pk2(w.z, w.w);
        bmA[j] = pk2(b.x, b.y); bmB[j] = pk2(b.z, b.w);
    }
    __syncthreads();

    for (int r = 0; r < 128; r++) {
        const float* xr = xs + r * 12;
        float delta = xr[10], phi = xr[11];
        unsigned long long d2 = pk2(delta, delta), p2 = pk2(phi, phi);
        unsigned long long aA, aB, t;
        FMA2(aA, d2, w1A, b1A);
        FMA2(aB, d2, w1B, b1B);
#pragma unroll
        for (int j = 0; j < NEXP; j++) {
            unsigned long long o2 = pk2(xr[j], xr[j]);
            FMA2(t, p2, wmA[j], bmA[j]);
            FMA2(aA, o2, t, aA);
            FMA2(t, p2, wmB[j], bmB[j]);
            FMA2(aB, o2, t, aB);
        }
        float a0, a1, a2, a3;
        upk2(a0, a1, aA); upk2(a2, a3, aB);
        __half2 h01 = __floats2half2_rn(fmaxf(a0, 0.f), fmaxf(a1, 0.f));
        __half2 h23 = __floats2half2_rn(fmaxf(a2, 0.f), fmaxf(a3, 0.f));
        uint2 o;
        o.x = *reinterpret_cast<uint32_t*>(&h01);
        o.y = *reinterpret_cast<uint32_t*>(&h23);
        *reinterpret_cast<uint2*>(g_h1 + (size_t)(b0 + r) * Hd + k0) = o;
    }
}

// ============================================================================
// Kernel 3: GEMM2 (mma.sync fp16) + bias + relu + fused W3 dot -> partials
// grid = (4 ntiles, 512 mblocks); CTA 128M x 256N, 512 thr / 16 warps.
// Warp tile 32x64 (4 m-rows x 4 n-cols of warps). 3-stage cp.async ring,
// one __syncthreads per chunk, loads issued 2 chunks ahead.
// ============================================================================
#define OFF_B2S 0
#define OFF_W30 1024
#define OFF_W31 2048
#define OFF_RED 3072             // 3 * 128 * float2 = 3 KB
#define OFF_STG 8192
#define STG_BYTES 49152          // A 16K | B 32K per stage
#define GEMM_SMEM (OFF_STG + NSTG * STG_BYTES)   // 155648

__global__ void __launch_bounds__(512, 1) gemm_kernel(
    const float* __restrict__ b2, const float* __restrict__ W3)
{
    extern __shared__ char smem[];
    const uint32_t sb = smem_u32(smem);
    const int tid = threadIdx.x, wid = tid >> 5, lane = tid & 31;
    const int ntile = blockIdx.x, mblock = blockIdx.y;
    const int m0 = mblock * 128, n0 = ntile * 256;
    const int warp_m = (wid & 3) * 32;       // 32 rows / warp
    const int warp_n = (wid >> 2) * 64;      // 64 cols / warp (4 warp-cols)

    float* b2s = reinterpret_cast<float*>(smem + OFF_B2S);
    float* w30 = reinterpret_cast<float*>(smem + OFF_W30);
    float* w31 = reinterpret_cast<float*>(smem + OFF_W31);
    float2* red = reinterpret_cast<float2*>(smem + OFF_RED);

    if (tid < 256) {
        b2s[tid] = b2[n0 + tid];
        w30[tid] = W3[n0 + tid];
        w31[tid] = W3[Hd + n0 + tid];
    }

    const __half* Ag = g_h1 + (size_t)m0 * Hd;
    const __half* Bg = g_W2h + (size_t)n0 * Hd;

    auto issue_chunk = [&](int kc, int s) {
        const int koff = kc * TKH;
        const uint32_t stgA = sb + OFF_STG + s * STG_BYTES;
        const uint32_t stgB = stgA + 16384;
#pragma unroll
        for (int i = 0; i < 2; i++) {                  // A: 128 rows x 8 segs
            int idx = tid + 512 * i;
            int r = idx >> 3, c = idx & 7;
            CP_ASYNC16(stgA + sw128(r * 128 + c * 16),
                       Ag + (size_t)r * Hd + koff + c * 8);
        }
#pragma unroll
        for (int i = 0; i < 4; i++) {                  // B: 256 rows x 8 segs
            int idx = tid + 512 * i;
            int r = idx >> 3, c = idx & 7;
            CP_ASYNC16(stgB + sw128(r * 128 + c * 16),
                       Bg + (size_t)r * Hd + koff + c * 8);
        }
        CP_COMMIT();
    };

    float c[2][8][4];
#pragma unroll
    for (int i = 0; i < 2; i++)
#pragma unroll
        for (int j = 0; j < 8; j++)
#pragma unroll
            for (int q = 0; q < 4; q++) c[i][j][q] = 0.f;

    const int a_row = lane & 15;
    const int a_seg = (lane >> 4) * 16;
    const int b_row = (lane & 7) + ((lane & 16) >> 1);
    const int b_seg = ((lane >> 3) & 1) * 16;

    issue_chunk(0, 0);
    issue_chunk(1, 1);

    for (int k = 0; k < NCHUNK; k++) {
        if (k == NCHUNK - 1) { CP_WAIT(0); } else { CP_WAIT(1); }
        __syncthreads();                       // all threads see chunk k; all done computing k-1
        if (k + 2 < NCHUNK) issue_chunk(k + 2, (k + 2) % NSTG);  // overwrites stage (k-1)%3: safe

        const uint32_t stgA = sb + OFF_STG + (k % NSTG) * STG_BYTES;
        const uint32_t stgB = stgA + 16384;

#pragma unroll
        for (int kk = 0; kk < 4; kk++) {               // 4 x k16 steps
            uint32_t a[2][4];
#pragma unroll
            for (int i = 0; i < 2; i++) {
                uint32_t byo = (warp_m + i * 16 + a_row) * 128 + kk * 32 + a_seg;
                LDMATRIX_X4(a[i][0], a[i][1], a[i][2], a[i][3], stgA + sw128(byo));
            }
            uint32_t bfr[8][2];
#pragma unroll
            for (int jj = 0; jj < 4; jj++) {
                uint32_t byo = (warp_n + jj * 16 + b_row) * 128 + kk * 32 + b_seg;
                uint32_t r0, r1, r2, r3;
                LDMATRIX_X4(r0, r1, r2, r3, stgB + sw128(byo));
                bfr[jj * 2][0] = r0;     bfr[jj * 2][1] = r1;
                bfr[jj * 2 + 1][0] = r2; bfr[jj * 2 + 1][1] = r3;
            }
#pragma unroll
            for (int i = 0; i < 2; i++)
#pragma unroll
                for (int j = 0; j < 8; j++)
                    MMA16816(c[i][j][0], c[i][j][1], c[i][j][2], c[i][j][3],
                             a[i][0], a[i][1], a[i][2], a[i][3],
                             bfr[j][0], bfr[j][1]);
        }
        // no trailing barrier: next iteration's barrier protects stage reuse
    }

    // ---- epilogue: relu(c + b2) dot W3 cols, fused in registers ----
    float o0[4] = {0.f, 0.f, 0.f, 0.f}, o1[4] = {0.f, 0.f, 0.f, 0.f};
#pragma unroll
    for (int i = 0; i < 2; i++) {
#pragma unroll
        for (int j = 0; j < 8; j++) {
            int cb = warp_n + j * 8 + (lane & 3) * 2;
            float bb0 = b2s[cb], bb1 = b2s[cb + 1];
            float wa0 = w30[cb], wa1 = w30[cb + 1];
            float wb0 = w31[cb], wb1 = w31[cb + 1];
            float v0 = fmaxf(c[i][j][0] + bb0, 0.f);
            float v1 = fmaxf(c[i][j][1] + bb1, 0.f);
            o0[i * 2]     = fmaf(v0, wa0, fmaf(v1, wa1, o0[i * 2]));
            o1[i * 2]     = fmaf(v0, wb0, fmaf(v1, wb1, o1[i * 2]));
            float v2 = fmaxf(c[i][j][2] + bb0, 0.f);
            float v3 = fmaxf(c[i][j][3] + bb1, 0.f);
            o0[i * 2 + 1] = fmaf(v2, wa0, fmaf(v3, wa1, o0[i * 2 + 1]));
            o1[i * 2 + 1] = fmaf(v2, wb0, fmaf(v3, wb1, o1[i * 2 + 1]));
        }
    }
#pragma unroll
    for (int q = 0; q < 4; q++) {
        o0[q] += __shfl_xor_sync(0xffffffffu, o0[q], 1);
        o0[q] += __shfl_xor_sync(0xffffffffu, o0[q], 2);
        o1[q] += __shfl_xor_sync(0xffffffffu, o1[q], 1);
        o1[q] += __shfl_xor_sync(0xffffffffu, o1[q], 2);
    }
    __syncthreads();                 // stages dead; smem reuse ordering
    const int wc = wid >> 2;         // warp column 0..3
    if (wc >= 1 && (lane & 3) == 0) {
#pragma unroll
        for (int q = 0; q < 4; q++) {
            int rl = warp_m + q * 8 + (lane >> 2);
            red[(wc - 1) * 128 + rl] = make_float2(o0[q], o1[q]);
        }
    }
    __syncthreads();
    if (wc == 0 && (lane & 3) == 0) {
#pragma unroll
        for (int q = 0; q < 4; q++) {
            int rl = warp_m + q * 8 + (lane >> 2);
            float2 r0 = red[rl];
            float2 r1 = red[128 + rl];
            float2 r2 = red[256 + rl];
            g_partial[(size_t)ntile * BSZ + m0 + rl] =
                make_float2(o0[q] + r0.x + r1.x + r2.x,
                            o1[q] + r0.y + r1.y + r2.y);
        }
    }
}

// ============================================================================
// Kernel 4: reduce partials over 4 ntiles, add b3 -> out (B x 2 fp32)
// ============================================================================
__global__ void __launch_bounds__(256) reduce_kernel(
    const float* __restrict__ b3, float* __restrict__ out)
{
    int i = blockIdx.x * 256 + threadIdx.x;          // 0..65535
    float s0 = b3[0], s1 = b3[1];
#pragma unroll
    for (int t = 0; t < NT; t++) {
        float2 p = g_partial[(size_t)t * BSZ + i];
        s0 += p.x; s1 += p.y;
    }
    out[2 * i]     = s0;
    out[2 * i + 1] = s1;
}

// ============================================================================
extern "C" void kernel_launch(void* const* d_in, const int* in_sizes, int n_in,
                              void* d_out, int out_size)
{
    const float* x   = (const float*)d_in[0];
    const float* W1  = (const float*)d_in[1];
    const float* b1  = (const float*)d_in[2];
    const float* Wm  = (const float*)d_in[3];
    const float* bm  = (const float*)d_in[4];
    const float* W2  = (const float*)d_in[5];
    const float* b2  = (const float*)d_in[6];
    const float* W3  = (const float*)d_in[7];
    const float* b3  = (const float*)d_in[8];
    float* out = (float*)d_out;

    cudaFuncSetAttribute(gemm_kernel, cudaFuncAttributeMaxDynamicSharedMemorySize, GEMM_SMEM);

    convert_w2_kernel<<<Hd * Hd / (256 * 4), 256>>>(W2);
    h1_kernel<<<BSZ / 128, 256>>>(x, W1, b1, Wm, bm);
    gemm_kernel<<<dim3(NT, BSZ / 128), 512, GEMM_SMEM>>>(b2, W3);
    reduce_kernel<<<BSZ / 256, 256>>>(b3, out);
}